// round 11
// baseline (speedup 1.0000x reference)
#include <cuda_runtime.h>
#include <cstdint>

// Inverse 3D Haar synthesis:
//   in  : [B=2, 8*16, T=8, H=128, W=128] fp32 (8 subbands of 16 channels)
//   out : [B=2, 16, 16, 256, 256] fp32
// out[b,g,2t+pt,2h+ph,2w+pw] = (1/8) * sum_s (-1)^(bt*pt+bh*ph+bw*pw) * x[b, s*16+g, t, h, w]
// with s = 4*bt + 2*bh + bw.
//
// Thread mapping: lane owns 4 consecutive input w -> 8 CONTIGUOUS output
// floats per (pt,ph) row. Loads: 8x LDG.128 (512B/warp dense). Stores: 4x
// 256-bit st.global.wt v8 (1KB/warp dense, write-through) so output reaches
// DRAM during the kernel instead of parking dirty in L2 and draining
// serially between graph replays.

__device__ __forceinline__ float4 f4add(float4 a, float4 b) {
    return make_float4(a.x + b.x, a.y + b.y, a.z + b.z, a.w + b.w);
}
__device__ __forceinline__ float4 f4sub(float4 a, float4 b) {
    return make_float4(a.x - b.x, a.y - b.y, a.z - b.z, a.w - b.w);
}

// 256-bit write-through store: interleave (e,o) pairs and scale by k.
__device__ __forceinline__ void st256_wt(float* p, float4 e, float4 o, float k) {
    asm volatile(
        "st.global.wt.v8.b32 [%0], {%1,%2,%3,%4,%5,%6,%7,%8};"
        :: "l"(p),
           "f"(e.x * k), "f"(o.x * k), "f"(e.y * k), "f"(o.y * k),
           "f"(e.z * k), "f"(o.z * k), "f"(e.w * k), "f"(o.w * k)
        : "memory");
}

__global__ __launch_bounds__(256) void ihaar3d_kernel(const float* __restrict__ x,
                                                      float* __restrict__ out) {
    // Decode: [b(1)][g(4)][t(3)][h(7)][w4(5)] bits -> 2^20 threads.
    const int idx = blockIdx.x * blockDim.x + threadIdx.x;
    const int w4 = idx & 31;
    const int h  = (idx >> 5) & 127;
    const int t  = (idx >> 12) & 7;
    const int g  = (idx >> 15) & 15;
    const int b  = (idx >> 19) & 1;

    const int w0 = w4 << 2;

    // input: [B, 128, 8, 128, 128]; subband stride = 16 channels. Offsets fit int32.
    const int SUB = 16 * 8 * 128 * 128;  // 2,097,152
    const int base = (((b * 128 + g) * 8 + t) * 128 + h) * 128 + w0;

    float4 v0 = *reinterpret_cast<const float4*>(x + base + 0 * SUB);  // lll
    float4 v1 = *reinterpret_cast<const float4*>(x + base + 1 * SUB);  // llh
    float4 v2 = *reinterpret_cast<const float4*>(x + base + 2 * SUB);  // lhl
    float4 v3 = *reinterpret_cast<const float4*>(x + base + 3 * SUB);  // lhh
    float4 v4 = *reinterpret_cast<const float4*>(x + base + 4 * SUB);  // hll
    float4 v5 = *reinterpret_cast<const float4*>(x + base + 5 * SUB);  // hlh
    float4 v6 = *reinterpret_cast<const float4*>(x + base + 6 * SUB);  // hhl
    float4 v7 = *reinterpret_cast<const float4*>(x + base + 7 * SUB);  // hhh

    // Stage 1: W butterfly (bit0).
    float4 ll_e = f4add(v0, v1), ll_o = f4sub(v0, v1);
    float4 lh_e = f4add(v2, v3), lh_o = f4sub(v2, v3);
    float4 hl_e = f4add(v4, v5), hl_o = f4sub(v4, v5);
    float4 hh_e = f4add(v6, v7), hh_o = f4sub(v6, v7);

    // Stage 2: H butterfly (bit1): index = ph.
    float4 le[2] = {f4add(ll_e, lh_e), f4sub(ll_e, lh_e)};
    float4 lo[2] = {f4add(ll_o, lh_o), f4sub(ll_o, lh_o)};
    float4 he[2] = {f4add(hl_e, hh_e), f4sub(hl_e, hh_e)};
    float4 ho[2] = {f4add(hl_o, hh_o), f4sub(hl_o, hh_o)};

    // Stage 3: T butterfly (bit2) + scale + dense 256-bit write-through stores.
    // out: [2, 16, 16, 256, 256]; lane chunk = 8 contiguous floats at 8*w4.
    const float k = 0.125f;
    const int obase = (((b * 16 + g) * 16 + 2 * t) * 256 + 2 * h) * 256 + (w4 << 3);
    const int PT = 256 * 256;
    const int PH = 256;

#pragma unroll
    for (int pt = 0; pt < 2; ++pt) {
#pragma unroll
        for (int ph = 0; ph < 2; ++ph) {
            float4 e = pt == 0 ? f4add(le[ph], he[ph]) : f4sub(le[ph], he[ph]);
            float4 o = pt == 0 ? f4add(lo[ph], ho[ph]) : f4sub(lo[ph], ho[ph]);
            st256_wt(out + obase + pt * PT + ph * PH, e, o, k);
        }
    }
}

extern "C" void kernel_launch(void* const* d_in, const int* in_sizes, int n_in,
                              void* d_out, int out_size) {
    const float* x = (const float*)d_in[0];
    float* out = (float*)d_out;
    // total threads = 2*16*8*128*32 = 1,048,576
    ihaar3d_kernel<<<4096, 256>>>(x, out);
}